// round 2
// baseline (speedup 1.0000x reference)
#include <cuda_runtime.h>
#include <cuda_bf16.h>

// Problem constants (fixed shapes from reference setup_inputs)
#define BATCH   2
#define H_IN    64
#define W_IN    64
#define C_IN    128
#define N_IN    (H_IN * W_IN * C_IN)          // 524288
#define HP      32
#define WP      32
#define N_POOL  (HP * WP * C_IN)              // 131072
#define N_OUT   32

// Output layout: [w_zero (B*N_IN*N_OUT)] [b_u_ (B*N_OUT)] [w_zero] [b_l_ (B*N_OUT)]
#define WZ_ELEMS  ((long long)BATCH * N_IN * N_OUT)     // 33554432
#define OFF_BU    (WZ_ELEMS)                            // 33554432
#define OFF_WZ2   (OFF_BU + (long long)BATCH * N_OUT)   // 33554496
#define OFF_BL    (OFF_WZ2 + WZ_ELEMS)                  // 67108928

// L2-resident scratch for pooled bounds (1 MB each)
__device__ float g_bu[BATCH * N_POOL];
__device__ float g_bl[BATCH * N_POOL];

// ---------------------------------------------------------------------------
// Kernel 1: 2x2 stride-2 NHWC maxpool of u_c and l_c -> g_bu, g_bl
// One thread per pooled element; coalesced over the C (innermost) dim.
// ---------------------------------------------------------------------------
__global__ void maxpool_kernel(const float* __restrict__ u,
                               const float* __restrict__ l) {
    int idx = blockIdx.x * blockDim.x + threadIdx.x;   // 0 .. BATCH*N_POOL-1
    if (idx >= BATCH * N_POOL) return;
    int b  = idx >> 17;           // / N_POOL (131072 = 2^17)
    int p  = idx & (N_POOL - 1);
    int c  = p & (C_IN - 1);
    int pw = (p >> 7) & (WP - 1);
    int ph = p >> 12;
    long long base = (long long)b * N_IN
                   + (long long)(2 * ph) * (W_IN * C_IN)
                   + (long long)(2 * pw) * C_IN + c;
    const int dW = C_IN;            // +1 in W
    const int dH = W_IN * C_IN;     // +1 in H

    float u0 = u[base], u1 = u[base + dW], u2 = u[base + dH], u3 = u[base + dH + dW];
    g_bu[idx] = fmaxf(fmaxf(u0, u1), fmaxf(u2, u3));
    float l0 = l[base], l1 = l[base + dW], l2 = l[base + dH], l3 = l[base + dH + dW];
    g_bl[idx] = fmaxf(fmaxf(l0, l1), fmaxf(l2, l3));
}

// ---------------------------------------------------------------------------
// Kernel 2: write the bias terms into the output bias slots (after memset)
// ---------------------------------------------------------------------------
__global__ void bias_init_kernel(const float* __restrict__ bu,
                                 const float* __restrict__ bl,
                                 float* __restrict__ out) {
    int i = threadIdx.x;                  // 0..63  (BATCH*N_OUT)
    if (i < BATCH * N_OUT) {
        out[OFF_BU + i] = bu[i];
        out[OFF_BL + i] = bl[i];
    }
}

// ---------------------------------------------------------------------------
// Kernel 3: fold backward weights into constant biases.
//   b_u_[b,o] += sum_p max(wu,0)*bu[p] + min(wu,0)*bl[p]
//   b_l_[b,o] += sum_p max(wl,0)*bl[p] + min(wl,0)*bu[p]
// Thread layout: tid%8 -> which float4 of the 32-wide N_OUT row,
//                tid/8 -> p offset within a 32-p slab.
// Each warp reads fully-coalesced 128B rows of both weight tensors.
// ---------------------------------------------------------------------------
#define R_CHUNKS   128                     // blocks per batch
#define R_THREADS  256
#define P_PER_BLK  (N_POOL / R_CHUNKS)     // 1024
#define P_PER_STEP (R_THREADS / 8)         // 32

__global__ __launch_bounds__(R_THREADS)
void reduce_kernel(const float4* __restrict__ wu,
                   const float4* __restrict__ wl,
                   float* __restrict__ out) {
    const int b   = blockIdx.y;
    const int tid = threadIdx.x;
    const int o4  = tid & 7;          // which float4 (o = o4*4 .. o4*4+3)
    const int pof = tid >> 3;         // 0..31

    __shared__ float s_u[N_OUT];
    __shared__ float s_l[N_OUT];
    if (tid < N_OUT) { s_u[tid] = 0.0f; s_l[tid] = 0.0f; }
    __syncthreads();

    const int p0 = blockIdx.x * P_PER_BLK;
    const long long wbase = (long long)b * N_POOL;

    float4 au = make_float4(0.f, 0.f, 0.f, 0.f);
    float4 al = make_float4(0.f, 0.f, 0.f, 0.f);

    #pragma unroll 4
    for (int it = 0; it < P_PER_BLK / P_PER_STEP; ++it) {
        int p = p0 + it * P_PER_STEP + pof;
        float bu = g_bu[wbase + p];
        float bl = g_bl[wbase + p];
        long long row = (wbase + p) * 8 + o4;   // float4 index
        float4 wuv = wu[row];
        float4 wlv = wl[row];

        au.x += fmaxf(wuv.x, 0.f) * bu + fminf(wuv.x, 0.f) * bl;
        au.y += fmaxf(wuv.y, 0.f) * bu + fminf(wuv.y, 0.f) * bl;
        au.z += fmaxf(wuv.z, 0.f) * bu + fminf(wuv.z, 0.f) * bl;
        au.w += fmaxf(wuv.w, 0.f) * bu + fminf(wuv.w, 0.f) * bl;

        al.x += fmaxf(wlv.x, 0.f) * bl + fminf(wlv.x, 0.f) * bu;
        al.y += fmaxf(wlv.y, 0.f) * bl + fminf(wlv.y, 0.f) * bu;
        al.z += fmaxf(wlv.z, 0.f) * bl + fminf(wlv.z, 0.f) * bu;
        al.w += fmaxf(wlv.w, 0.f) * bl + fminf(wlv.w, 0.f) * bu;
    }

    int ob = o4 * 4;
    atomicAdd(&s_u[ob + 0], au.x);
    atomicAdd(&s_u[ob + 1], au.y);
    atomicAdd(&s_u[ob + 2], au.z);
    atomicAdd(&s_u[ob + 3], au.w);
    atomicAdd(&s_l[ob + 0], al.x);
    atomicAdd(&s_l[ob + 1], al.y);
    atomicAdd(&s_l[ob + 2], al.z);
    atomicAdd(&s_l[ob + 3], al.w);
    __syncthreads();

    if (tid < N_OUT) {
        atomicAdd(&out[OFF_BU + b * N_OUT + tid], s_u[tid]);
        atomicAdd(&out[OFF_BL + b * N_OUT + tid], s_l[tid]);
    }
}

// ---------------------------------------------------------------------------
extern "C" void kernel_launch(void* const* d_in, const int* in_sizes, int n_in,
                              void* d_out, int out_size) {
    // Input order: y, x_0, u_c, l_c, w_out_u, b_out_u, w_out_l, b_out_l
    const float* u_c     = (const float*)d_in[2];
    const float* l_c     = (const float*)d_in[3];
    const float* w_out_u = (const float*)d_in[4];
    const float* b_out_u = (const float*)d_in[5];
    const float* w_out_l = (const float*)d_in[6];
    const float* b_out_l = (const float*)d_in[7];
    float* out = (float*)d_out;

    // 1) Zero the whole output (both w_zero blocks; bias slots overwritten next).
    cudaMemsetAsync(d_out, 0, (size_t)out_size * sizeof(float), 0);

    // 2) Pooled interval bounds.
    maxpool_kernel<<<(BATCH * N_POOL + 255) / 256, 256>>>(u_c, l_c);

    // 3) Bias slots = b_out_u / b_out_l.
    bias_init_kernel<<<1, 64>>>(b_out_u, b_out_l, out);

    // 4) Fold weights into biases.
    dim3 grid(R_CHUNKS, BATCH);
    reduce_kernel<<<grid, R_THREADS>>>((const float4*)w_out_u,
                                       (const float4*)w_out_l, out);
}

// round 3
// speedup vs baseline: 1.0268x; 1.0268x over previous
#include <cuda_runtime.h>

// Fixed shapes from reference setup_inputs
#define BATCH   2
#define H_IN    64
#define W_IN    64
#define C_IN    128
#define N_IN    (H_IN * W_IN * C_IN)          // 524288
#define N_POOL  131072                        // 32*32*128
#define N_OUT   32

// Output layout: [w_zero (B*N_IN*N_OUT)] [b_u_ (B*N_OUT)] [w_zero] [b_l_ (B*N_OUT)]
#define WZ_ELEMS  ((long long)BATCH * N_IN * N_OUT)     // 33554432
#define OFF_BU    (WZ_ELEMS)                            // 33554432
#define OFF_WZ2   (OFF_BU + (long long)BATCH * N_OUT)   // 33554496
#define OFF_BL    (OFF_WZ2 + WZ_ELEMS)                  // 67108928

// float4-granular zero regions (both 16B aligned):
//   region0: float4 [0, 8388608)            -> floats [0, OFF_BU)
//   region1: float4 [8388624, 16777232)     -> floats [OFF_WZ2, OFF_BL)
#define REGION4      8388608LL
#define REGION1_OFF  8388624LL
#define TOTAL4       (2LL * REGION4)

#define NBLK_X     148
#define R_THREADS  256
#define P_PER_BLK  886          // ceil(131072/148)
#define ZSTRIDE    ((long long)NBLK_X * BATCH * R_THREADS)   // 75776

// ---------------------------------------------------------------------------
// Prologue: write bias terms into the output bias slots (fused kernel then
// atomicAdds the folded-weight sums on top). Must run BEFORE fused kernel.
// ---------------------------------------------------------------------------
__global__ void bias_init_kernel(const float* __restrict__ bu,
                                 const float* __restrict__ bl,
                                 float* __restrict__ out) {
    int i = threadIdx.x;                  // 0..63  (BATCH*N_OUT)
    if (i < BATCH * N_OUT) {
        out[OFF_BU + i] = bu[i];
        out[OFF_BL + i] = bl[i];
    }
}

// ---------------------------------------------------------------------------
// Fused kernel: inline 2x2 maxpool + weight fold + interleaved output zeroing.
// grid = (148, BATCH), 256 threads.
//   tid & 7  -> which float4 of the 32-wide N_OUT row
//   tid >> 3 -> p offset within a 32-p step
// Zero stores (float4, streaming) are interleaved into the reduction loop so
// HBM read and write streams overlap.
// ---------------------------------------------------------------------------
__global__ __launch_bounds__(R_THREADS)
void fused_kernel(const float* __restrict__ u,
                  const float* __restrict__ l,
                  const float4* __restrict__ wu,
                  const float4* __restrict__ wl,
                  float* __restrict__ out) {
    const int b   = blockIdx.y;
    const int tid = threadIdx.x;
    const int o4  = tid & 7;
    const int pof = tid >> 3;

    float4* out4 = (float4*)out;
    const float4 zv = make_float4(0.f, 0.f, 0.f, 0.f);
    long long zidx = ((long long)(b * NBLK_X + blockIdx.x)) * R_THREADS + tid;

    const int p_begin = blockIdx.x * P_PER_BLK;
    const int p_end   = min(p_begin + P_PER_BLK, N_POOL);

    const long long wbase = (long long)b * N_POOL;
    const float* ub = u + (long long)b * N_IN;
    const float* lb = l + (long long)b * N_IN;

    float4 au = zv, al = zv;

    for (int p = p_begin + pof; p < p_end; p += 32) {
        // inline 2x2 stride-2 NHWC maxpool
        int c  = p & 127;
        int pw = (p >> 7) & 31;
        int ph = p >> 12;
        int base = (ph << 14) + (pw << 8) + c;   // 2*ph*(64*128) + 2*pw*128 + c
        float bu = fmaxf(fmaxf(__ldg(ub + base),        __ldg(ub + base + 128)),
                         fmaxf(__ldg(ub + base + 8192), __ldg(ub + base + 8320)));
        float bl = fmaxf(fmaxf(__ldg(lb + base),        __ldg(lb + base + 128)),
                         fmaxf(__ldg(lb + base + 8192), __ldg(lb + base + 8320)));

        long long row = (wbase + p) * 8 + o4;
        float4 wuv = __ldcs(wu + row);
        float4 wlv = __ldcs(wl + row);

        au.x += fmaxf(wuv.x, 0.f) * bu + fminf(wuv.x, 0.f) * bl;
        au.y += fmaxf(wuv.y, 0.f) * bu + fminf(wuv.y, 0.f) * bl;
        au.z += fmaxf(wuv.z, 0.f) * bu + fminf(wuv.z, 0.f) * bl;
        au.w += fmaxf(wuv.w, 0.f) * bu + fminf(wuv.w, 0.f) * bl;

        al.x += fmaxf(wlv.x, 0.f) * bl + fminf(wlv.x, 0.f) * bu;
        al.y += fmaxf(wlv.y, 0.f) * bl + fminf(wlv.y, 0.f) * bu;
        al.z += fmaxf(wlv.z, 0.f) * bl + fminf(wlv.z, 0.f) * bu;
        al.w += fmaxf(wlv.w, 0.f) * bl + fminf(wlv.w, 0.f) * bu;

        // interleaved streaming zero stores (8 x 16B per thread per iter)
        #pragma unroll
        for (int k = 0; k < 8; ++k) {
            if (zidx < TOTAL4) {
                long long off = zidx & (REGION4 - 1);
                long long oi  = (zidx >> 23) ? (REGION1_OFF + off) : off;
                __stcs(out4 + oi, zv);
                zidx += ZSTRIDE;
            }
        }
    }

    // drain any remaining zero stores
    for (; zidx < TOTAL4; zidx += ZSTRIDE) {
        long long off = zidx & (REGION4 - 1);
        long long oi  = (zidx >> 23) ? (REGION1_OFF + off) : off;
        __stcs(out4 + oi, zv);
    }

    // block-level bias reduction, then global atomics onto pre-initialized slots
    __shared__ float s_u[N_OUT];
    __shared__ float s_l[N_OUT];
    if (tid < N_OUT) { s_u[tid] = 0.0f; s_l[tid] = 0.0f; }
    __syncthreads();

    int ob = o4 * 4;
    atomicAdd(&s_u[ob + 0], au.x);
    atomicAdd(&s_u[ob + 1], au.y);
    atomicAdd(&s_u[ob + 2], au.z);
    atomicAdd(&s_u[ob + 3], au.w);
    atomicAdd(&s_l[ob + 0], al.x);
    atomicAdd(&s_l[ob + 1], al.y);
    atomicAdd(&s_l[ob + 2], al.z);
    atomicAdd(&s_l[ob + 3], al.w);
    __syncthreads();

    if (tid < N_OUT) {
        atomicAdd(&out[OFF_BU + b * N_OUT + tid], s_u[tid]);
        atomicAdd(&out[OFF_BL + b * N_OUT + tid], s_l[tid]);
    }
}

// ---------------------------------------------------------------------------
extern "C" void kernel_launch(void* const* d_in, const int* in_sizes, int n_in,
                              void* d_out, int out_size) {
    // Input order: y, x_0, u_c, l_c, w_out_u, b_out_u, w_out_l, b_out_l
    const float* u_c     = (const float*)d_in[2];
    const float* l_c     = (const float*)d_in[3];
    const float* w_out_u = (const float*)d_in[4];
    const float* b_out_u = (const float*)d_in[5];
    const float* w_out_l = (const float*)d_in[6];
    const float* b_out_l = (const float*)d_in[7];
    float* out = (float*)d_out;

    // 1) Bias slots = b_out_u / b_out_l (fused kernel atomicAdds on top).
    bias_init_kernel<<<1, 64>>>(b_out_u, b_out_l, out);

    // 2) Everything else in one pass: inline maxpool + weight fold + zeroing.
    dim3 grid(NBLK_X, BATCH);
    fused_kernel<<<grid, R_THREADS>>>(u_c, l_c,
                                      (const float4*)w_out_u,
                                      (const float4*)w_out_l, out);
}